// round 2
// baseline (speedup 1.0000x reference)
#include <cuda_runtime.h>
#include <cstdint>

#define NPTS 4096
#define DDIM 64

// ---------------- device scratch ----------------
__device__ float g_sqnorm[NPTS];          // per-row squared norms
__device__ float g_partial_sq[16];        // per-block partial sums of sq norms
__device__ float g_partial_col[16][64];   // per-block partial column sums
__device__ float g_c;                     // log2(e) / (4*bw)

// ---------------- kernel 1: row sq-norms + partial column sums ----------------
__global__ void prologue_kernel(const float* __restrict__ X) {
    const int tid = threadIdx.x;
    const int r = blockIdx.x * 256 + tid;
    const int lane = tid & 31;
    const int warp = tid >> 5;

    float4 v[16];
    const float4* p = (const float4*)(X + (size_t)r * DDIM);
    float s = 0.f;
#pragma unroll
    for (int i = 0; i < 16; i++) {
        v[i] = p[i];
        s += v[i].x * v[i].x + v[i].y * v[i].y + v[i].z * v[i].z + v[i].w * v[i].w;
    }
    g_sqnorm[r] = s;

    // block-reduce s -> g_partial_sq
    __shared__ float red[256];
    red[tid] = s;
    __syncthreads();
#pragma unroll
    for (int off = 128; off > 0; off >>= 1) {
        if (tid < off) red[tid] += red[tid + off];
        __syncthreads();
    }
    if (tid == 0) g_partial_sq[blockIdx.x] = red[0];

    // warp butterfly: sum the 64-vector across the 32 lanes of each warp
#pragma unroll
    for (int st = 16; st >= 1; st >>= 1) {
#pragma unroll
        for (int i = 0; i < 16; i++) {
            v[i].x += __shfl_xor_sync(0xffffffffu, v[i].x, st);
            v[i].y += __shfl_xor_sync(0xffffffffu, v[i].y, st);
            v[i].z += __shfl_xor_sync(0xffffffffu, v[i].z, st);
            v[i].w += __shfl_xor_sync(0xffffffffu, v[i].w, st);
        }
    }
    __shared__ float colp[8][64];
    if (lane == 0) {
#pragma unroll
        for (int i = 0; i < 16; i++) {
            colp[warp][i * 4 + 0] = v[i].x;
            colp[warp][i * 4 + 1] = v[i].y;
            colp[warp][i * 4 + 2] = v[i].z;
            colp[warp][i * 4 + 3] = v[i].w;
        }
    }
    __syncthreads();
    if (tid < 64) {
        float t = 0.f;
#pragma unroll
        for (int w = 0; w < 8; w++) t += colp[w][tid];
        g_partial_col[blockIdx.x][tid] = t;
    }
}

// ---------------- kernel 2: bandwidth -> exp2 coefficient ----------------
__global__ void finalize_kernel() {
    const int lane = threadIdx.x;  // 32 threads
    float t1 = 0.f, t2 = 0.f;
#pragma unroll
    for (int b = 0; b < 16; b++) {
        t1 += g_partial_col[b][lane];
        t2 += g_partial_col[b][lane + 32];
    }
    float cs = t1 * t1 + t2 * t2;
    float sv = (lane < 16) ? g_partial_sq[lane] : 0.f;
#pragma unroll
    for (int off = 16; off >= 1; off >>= 1) {
        cs += __shfl_xor_sync(0xffffffffu, cs, off);
        sv += __shfl_xor_sync(0xffffffffu, sv, off);
    }
    if (lane == 0) {
        // sum(L2) = 2*N*sum(||xi||^2) - 2*||sum xi||^2  (clamp effect negligible)
        float bwsum = 2.f * (float)NPTS * sv - 2.f * cs;
        float bw = bwsum / ((float)NPTS * (float)(NPTS - 1));
        g_c = 1.4426950408889634f / (4.f * bw);
    }
}

// ---------------- kernel 3: fused Gram + RBF-sum ----------------
// 128x128 tile, 256 threads, 4+4 split fragments (conflict-free LDS.128),
// XOR-swizzled k-major smem, register prefetch of second K chunk.
#define SWZ(k) ((((k) >> 2) & 7) << 2)

__global__ __launch_bounds__(256, 2)
void rbf_main_kernel(const float* __restrict__ X, float* __restrict__ out) {
    __shared__ float As[32][128];   // k-major, swizzled columns
    __shared__ float Bs[32][128];
    __shared__ float sqa[128];
    __shared__ float sqb[128];

    const int tid = threadIdx.x;
    const int tx = tid & 15;          // col group
    const int ty = tid >> 4;          // row group
    const int rowBase = blockIdx.y << 7;
    const int colBase = blockIdx.x << 7;

    if (tid < 128) sqa[tid] = g_sqnorm[rowBase + tid];
    else           sqb[tid - 128] = g_sqnorm[colBase + tid - 128];

    float acc[8][8];
#pragma unroll
    for (int i = 0; i < 8; i++)
#pragma unroll
        for (int j = 0; j < 8; j++) acc[i][j] = 0.f;

    float4 pa[4], pb[4];
    // ---- load chunk 0 (k = 0..31) ----
#pragma unroll
    for (int i = 0; i < 4; i++) {
        int idx = tid + (i << 8);
        int r = idx >> 3, f = idx & 7;
        pa[i] = *(const float4*)(X + (size_t)(rowBase + r) * DDIM + (f << 2));
        pb[i] = *(const float4*)(X + (size_t)(colBase + r) * DDIM + (f << 2));
    }
#pragma unroll
    for (int i = 0; i < 4; i++) {
        int idx = tid + (i << 8);
        int r = idx >> 3, f = idx & 7;
        int cs = r ^ (f << 2);
        As[f * 4 + 0][cs] = pa[i].x; As[f * 4 + 1][cs] = pa[i].y;
        As[f * 4 + 2][cs] = pa[i].z; As[f * 4 + 3][cs] = pa[i].w;
        Bs[f * 4 + 0][cs] = pb[i].x; Bs[f * 4 + 1][cs] = pb[i].y;
        Bs[f * 4 + 2][cs] = pb[i].z; Bs[f * 4 + 3][cs] = pb[i].w;
    }
    __syncthreads();

    // ---- prefetch chunk 1 (k = 32..63) into registers ----
#pragma unroll
    for (int i = 0; i < 4; i++) {
        int idx = tid + (i << 8);
        int r = idx >> 3, f = idx & 7;
        pa[i] = *(const float4*)(X + (size_t)(rowBase + r) * DDIM + 32 + (f << 2));
        pb[i] = *(const float4*)(X + (size_t)(colBase + r) * DDIM + 32 + (f << 2));
    }

    // ---- compute chunk 0 ----
#pragma unroll
    for (int k = 0; k < 32; k++) {
        int s = SWZ(k);
        float4 a0 = *(const float4*)&As[k][(ty << 2) ^ s];
        float4 a1 = *(const float4*)&As[k][((ty << 2) + 64) ^ s];
        float4 b0 = *(const float4*)&Bs[k][(tx << 2) ^ s];
        float4 b1 = *(const float4*)&Bs[k][((tx << 2) + 64) ^ s];
        float a[8] = {a0.x, a0.y, a0.z, a0.w, a1.x, a1.y, a1.z, a1.w};
        float b[8] = {b0.x, b0.y, b0.z, b0.w, b1.x, b1.y, b1.z, b1.w};
#pragma unroll
        for (int i = 0; i < 8; i++)
#pragma unroll
            for (int j = 0; j < 8; j++)
                acc[i][j] = fmaf(a[i], b[j], acc[i][j]);
    }
    __syncthreads();

    // ---- store chunk 1 ----
#pragma unroll
    for (int i = 0; i < 4; i++) {
        int idx = tid + (i << 8);
        int r = idx >> 3, f = idx & 7;
        int cs = r ^ (f << 2);
        As[f * 4 + 0][cs] = pa[i].x; As[f * 4 + 1][cs] = pa[i].y;
        As[f * 4 + 2][cs] = pa[i].z; As[f * 4 + 3][cs] = pa[i].w;
        Bs[f * 4 + 0][cs] = pb[i].x; Bs[f * 4 + 1][cs] = pb[i].y;
        Bs[f * 4 + 2][cs] = pb[i].z; Bs[f * 4 + 3][cs] = pb[i].w;
    }
    __syncthreads();

    // ---- compute chunk 1 ----
#pragma unroll
    for (int k = 0; k < 32; k++) {
        int s = SWZ(k);
        float4 a0 = *(const float4*)&As[k][(ty << 2) ^ s];
        float4 a1 = *(const float4*)&As[k][((ty << 2) + 64) ^ s];
        float4 b0 = *(const float4*)&Bs[k][(tx << 2) ^ s];
        float4 b1 = *(const float4*)&Bs[k][((tx << 2) + 64) ^ s];
        float a[8] = {a0.x, a0.y, a0.z, a0.w, a1.x, a1.y, a1.z, a1.w};
        float b[8] = {b0.x, b0.y, b0.z, b0.w, b1.x, b1.y, b1.z, b1.w};
#pragma unroll
        for (int i = 0; i < 8; i++)
#pragma unroll
            for (int j = 0; j < 8; j++)
                acc[i][j] = fmaf(a[i], b[j], acc[i][j]);
    }

    // ---- epilogue: L2 -> t = 2^(-L2*c); out = t + t^2 + t^4 + t^8 + t^16 ----
    const float c = g_c;
#pragma unroll
    for (int ii = 0; ii < 8; ii++) {
        const int rloc = (ty << 2) + (ii & 3) + ((ii >> 2) << 6);
        const float sa = sqa[rloc];
        float r0[4], r1[4];
#pragma unroll
        for (int j = 0; j < 4; j++) {
            {
                float l2 = fmaxf(sa + sqb[(tx << 2) + j] - 2.f * acc[ii][j], 0.f);
                float t;
                asm("ex2.approx.ftz.f32 %0, %1;" : "=f"(t) : "f"(-l2 * c));
                float t2 = t * t, t4 = t2 * t2, t8 = t4 * t4, t16 = t8 * t8;
                r0[j] = t + t2 + t4 + t8 + t16;
            }
            {
                float l2 = fmaxf(sa + sqb[64 + (tx << 2) + j] - 2.f * acc[ii][j + 4], 0.f);
                float t;
                asm("ex2.approx.ftz.f32 %0, %1;" : "=f"(t) : "f"(-l2 * c));
                float t2 = t * t, t4 = t2 * t2, t8 = t4 * t4, t16 = t8 * t8;
                r1[j] = t + t2 + t4 + t8 + t16;
            }
        }
        float* orow = out + (size_t)(rowBase + rloc) * NPTS + colBase + (tx << 2);
        *(float4*)(orow)      = *(float4*)&r0[0];
        *(float4*)(orow + 64) = *(float4*)&r1[0];
    }
}

// ---------------- launch ----------------
extern "C" void kernel_launch(void* const* d_in, const int* in_sizes, int n_in,
                              void* d_out, int out_size) {
    const float* X = (const float*)d_in[0];
    float* out = (float*)d_out;

    prologue_kernel<<<16, 256>>>(X);
    finalize_kernel<<<1, 32>>>();
    dim3 grid(NPTS / 128, NPTS / 128);
    rbf_main_kernel<<<grid, 256>>>(X, out);
}

// round 4
// speedup vs baseline: 3.1317x; 3.1317x over previous
#include <cuda_runtime.h>
#include <cstdint>

#define NPTS 4096
#define DDIM 64
#define LDT 68   // padded smem stride (floats): conflict-free fragment loads

// ---------------- device scratch ----------------
__device__ float g_sqnorm[NPTS];
__device__ float g_partial_sq[64];
__device__ float g_partial_col[64][64];
__device__ float g_c;   // log2(e)/(4*bw)

__device__ __forceinline__ uint32_t to_tf32(float f) {
    uint32_t o; asm("cvt.rna.tf32.f32 %0, %1;" : "=r"(o) : "f"(f)); return o;
}

// ---------------- prologue: sq norms + column partial sums (one pass) ----------------
// grid 64 x 256: block handles 64 rows; thread t -> row t/4, quarter t%4 (16 floats)
__global__ void prologue_kernel(const float* __restrict__ X) {
    const int tid = threadIdx.x;
    const int row = blockIdx.x * 64 + (tid >> 2);
    const int q = tid & 3;
    const int warp = tid >> 5, lane = tid & 31;

    float v[16];
    const float4* p = (const float4*)(X + (size_t)row * DDIM + q * 16);
    float s = 0.f;
#pragma unroll
    for (int i = 0; i < 4; i++) {
        float4 f = p[i];
        v[i * 4 + 0] = f.x; v[i * 4 + 1] = f.y; v[i * 4 + 2] = f.z; v[i * 4 + 3] = f.w;
        s += f.x * f.x + f.y * f.y + f.z * f.z + f.w * f.w;
    }
    float st = s;
    st += __shfl_xor_sync(0xffffffffu, st, 1);
    st += __shfl_xor_sync(0xffffffffu, st, 2);
    if (q == 0) g_sqnorm[row] = st;

    __shared__ float red[256];
    red[tid] = s;
    __syncthreads();
#pragma unroll
    for (int off = 128; off > 0; off >>= 1) {
        if (tid < off) red[tid] += red[tid + off];
        __syncthreads();
    }
    if (tid == 0) g_partial_sq[blockIdx.x] = red[0];

#pragma unroll
    for (int stp = 4; stp <= 16; stp <<= 1)
#pragma unroll
        for (int i = 0; i < 16; i++)
            v[i] += __shfl_xor_sync(0xffffffffu, v[i], stp);
    __shared__ float colp[8][64];
    if (lane < 4) {
#pragma unroll
        for (int i = 0; i < 16; i++) colp[warp][lane * 16 + i] = v[i];
    }
    __syncthreads();
    if (tid < 64) {
        float t = 0.f;
#pragma unroll
        for (int w = 0; w < 8; w++) t += colp[w][tid];
        g_partial_col[blockIdx.x][tid] = t;
    }
}

// ---------------- finalize ----------------
__global__ void finalize_kernel() {
    const int c = threadIdx.x;  // 64 threads
    float cs = 0.f;
#pragma unroll
    for (int b = 0; b < 64; b++) cs += g_partial_col[b][c];
    cs = cs * cs;
    float sv = g_partial_sq[c];
    __shared__ float r1[64], r2[64];
    r1[c] = cs; r2[c] = sv;
    __syncthreads();
#pragma unroll
    for (int off = 32; off > 0; off >>= 1) {
        if (c < off) { r1[c] += r1[c + off]; r2[c] += r2[c + off]; }
        __syncthreads();
    }
    if (c == 0) {
        // sum(L2) = 2*N*sum(||xi||^2) - 2*||sum xi||^2 (clamp effect negligible)
        float bwsum = 2.f * (float)NPTS * r2[0] - 2.f * r1[0];
        float bw = bwsum / ((float)NPTS * (float)(NPTS - 1));
        g_c = 1.4426950408889634f / (4.f * bw);
    }
}

// ---------------- main: tf32 mma.sync Gram + fused RBF epilogue ----------------
// 128x128 tile per CTA, 256 threads = 8 warps (4 row-groups x 2 col-groups).
// Warp tile 32x64 -> 2x8 m16n8k8 mma tiles, K=64 in 8 steps.
__global__ __launch_bounds__(256, 2)
void rbf_mma_kernel(const float* __restrict__ X, float* __restrict__ out) {
    extern __shared__ float smem[];
    float* As = smem;                 // [128][LDT]
    float* Bs = smem + 128 * LDT;     // [128][LDT]
    __shared__ float sqa[128], sqb[128];

    const int tid = threadIdx.x;
    const int wid = tid >> 5, lane = tid & 31;
    const int g = lane >> 2, t = lane & 3;          // fragment coords
    const int warpRow = (wid & 3) << 5;             // 0,32,64,96
    const int warpCol = (wid >> 2) << 6;            // 0,64
    const int rowBase = blockIdx.y << 7, colBase = blockIdx.x << 7;

    if (tid < 128) sqa[tid] = g_sqnorm[rowBase + tid];
    else           sqb[tid - 128] = g_sqnorm[colBase + tid - 128];

    // fill tiles (tf32-converted), 8 float4 per thread per operand
#pragma unroll
    for (int i = 0; i < 8; i++) {
        int idx = tid + (i << 8);          // 0..2047
        int r = idx >> 4, f = idx & 15;
        float4 va = *(const float4*)(X + (size_t)(rowBase + r) * DDIM + (f << 2));
        float4 vb = *(const float4*)(X + (size_t)(colBase + r) * DDIM + (f << 2));
        uint4 ta = { to_tf32(va.x), to_tf32(va.y), to_tf32(va.z), to_tf32(va.w) };
        uint4 tb = { to_tf32(vb.x), to_tf32(vb.y), to_tf32(vb.z), to_tf32(vb.w) };
        *(uint4*)(As + r * LDT + (f << 2)) = ta;
        *(uint4*)(Bs + r * LDT + (f << 2)) = tb;
    }
    __syncthreads();

    float acc[2][8][4];
#pragma unroll
    for (int m = 0; m < 2; m++)
#pragma unroll
        for (int n = 0; n < 8; n++)
#pragma unroll
            for (int j = 0; j < 4; j++) acc[m][n][j] = 0.f;

#pragma unroll
    for (int ks = 0; ks < 8; ks++) {
        const int k0 = ks << 3;
        uint32_t af[2][4], bf[8][2];
#pragma unroll
        for (int m = 0; m < 2; m++) {
            const float* ap = As + (size_t)(warpRow + (m << 4) + g) * LDT + k0 + t;
            af[m][0] = __float_as_uint(ap[0]);
            af[m][1] = __float_as_uint(ap[8 * LDT]);
            af[m][2] = __float_as_uint(ap[4]);
            af[m][3] = __float_as_uint(ap[8 * LDT + 4]);
        }
#pragma unroll
        for (int n = 0; n < 8; n++) {
            const float* bp = Bs + (size_t)(warpCol + (n << 3) + g) * LDT + k0 + t;
            bf[n][0] = __float_as_uint(bp[0]);
            bf[n][1] = __float_as_uint(bp[4]);
        }
#pragma unroll
        for (int m = 0; m < 2; m++)
#pragma unroll
            for (int n = 0; n < 8; n++) {
                asm volatile(
                    "mma.sync.aligned.m16n8k8.row.col.f32.tf32.tf32.f32 "
                    "{%0,%1,%2,%3}, {%4,%5,%6,%7}, {%8,%9}, {%0,%1,%2,%3};"
                    : "+f"(acc[m][n][0]), "+f"(acc[m][n][1]),
                      "+f"(acc[m][n][2]), "+f"(acc[m][n][3])
                    : "r"(af[m][0]), "r"(af[m][1]), "r"(af[m][2]), "r"(af[m][3]),
                      "r"(bf[n][0]), "r"(bf[n][1]));
            }
    }

    // ---- epilogue: L2 -> t = 2^(-L2*c); out = t + t^2 + t^4 + t^8 + t^16 ----
    const float cc = g_c;
#pragma unroll
    for (int m = 0; m < 2; m++) {
        const int r0 = warpRow + (m << 4) + g;       // rows r0, r0+8
        const float sa0 = sqa[r0], sa1 = sqa[r0 + 8];
#pragma unroll
        for (int n = 0; n < 8; n++) {
            const int c0 = warpCol + (n << 3) + (t << 1);
            const float sb0 = sqb[c0], sb1 = sqb[c0 + 1];
            float r[4];
            const float sas[4] = { sa0, sa0, sa1, sa1 };
            const float sbs[4] = { sb0, sb1, sb0, sb1 };
#pragma unroll
            for (int j = 0; j < 4; j++) {
                float l2 = fmaxf(sas[j] + sbs[j] - 2.f * acc[m][n][j], 0.f);
                float e;
                asm("ex2.approx.ftz.f32 %0, %1;" : "=f"(e) : "f"(-l2 * cc));
                float e2 = e * e, e4 = e2 * e2, e8 = e4 * e4, e16 = e8 * e8;
                r[j] = e + e2 + e4 + e8 + e16;
            }
            float* o0 = out + (size_t)(rowBase + r0) * NPTS + colBase + c0;
            float* o1 = out + (size_t)(rowBase + r0 + 8) * NPTS + colBase + c0;
            *(float2*)o0 = make_float2(r[0], r[1]);
            *(float2*)o1 = make_float2(r[2], r[3]);
        }
    }
}

// ---------------- launch ----------------
extern "C" void kernel_launch(void* const* d_in, const int* in_sizes, int n_in,
                              void* d_out, int out_size) {
    const float* X = (const float*)d_in[0];
    float* out = (float*)d_out;

    const int smem_bytes = 2 * 128 * LDT * sizeof(float);   // 69632
    cudaFuncSetAttribute(rbf_mma_kernel, cudaFuncAttributeMaxDynamicSharedMemorySize, smem_bytes);

    prologue_kernel<<<64, 256>>>(X);
    finalize_kernel<<<1, 64>>>();
    dim3 grid(NPTS / 128, NPTS / 128);
    rbf_mma_kernel<<<grid, 256, smem_bytes>>>(X, out);
}